// round 11
// baseline (speedup 1.0000x reference)
#include <cuda_runtime.h>
#include <cstdint>

// CostVolume2D: out[n, dy*9+dx, h, w] = mean_c f1[n,c,h,w] * f2pad[n,c,h+dy,w+dx]
// N=8, C=128, H=96, W=224, D=4 -> 81 channels. fp32.
//
// R11 = R8 (best: 134.2us) +
//  - depth-3 cp.async ring => ONE __syncthreads per chunk (was two), staging
//    issued before compute (more in-flight slack)
//  - ulonglong2 smem loads: a-pairs / even pairs born as aligned reg pairs
//  - R8's precomputed staging descriptors kept (R9 showed recompute costs ALU)

#define N_ 8
#define C_ 128
#define H_ 96
#define W_ 224

constexpr int TH = 16;
constexpr int TW = 32;
constexpr int DG = 3;          // dy per block (9 split across gridDim.z)
constexpr int CCH = 4;         // channels per pipeline stage
constexpr int NCHUNK = C_ / CCH;   // 32
constexpr int NBUF = 3;        // ring depth
constexpr int THREADS = 128;   // blockDim = (8,16)
constexpr int RW  = TW + 8;    // 40 padded row
constexpr int S2R = TH + 2;    // 18 rows
constexpr int F2_F4 = CCH * S2R * (RW / 4);  // 720
constexpr int F1_F4 = CCH * TH * (TW / 4);   // 512

__device__ __forceinline__ void cp_async16(uint32_t dst, const void* src, bool pred) {
    int sz = pred ? 16 : 0;
    asm volatile("cp.async.cg.shared.global [%0], [%1], 16, %2;\n"
                 :: "r"(dst), "l"(src), "r"(sz));
}
__device__ __forceinline__ void cp_commit() {
    asm volatile("cp.async.commit_group;\n" ::);
}
__device__ __forceinline__ void cp_wait1() {
    asm volatile("cp.async.wait_group 1;\n" ::);
}

__device__ __forceinline__ uint64_t pk2(float lo, float hi) {
    uint64_t r; asm("mov.b64 %0, {%1, %2};" : "=l"(r) : "f"(lo), "f"(hi)); return r;
}
__device__ __forceinline__ void fma2(uint64_t& acc, uint64_t a, uint64_t b) {
    asm("fma.rn.f32x2 %0, %1, %2, %0;" : "+l"(acc) : "l"(a), "l"(b));
}
__device__ __forceinline__ void upk(uint64_t v, float& lo, float& hi) {
    asm("mov.b64 {%0, %1}, %2;" : "=f"(lo), "=f"(hi) : "l"(v));
}

__global__ __launch_bounds__(THREADS, 3)
void costvol_kernel(const float* __restrict__ f1,
                    const float* __restrict__ f2,
                    float* __restrict__ out)
{
    __shared__ __align__(16) float s1[NBUF][CCH][TH][TW];   // 24 KB
    __shared__ __align__(16) float s2[NBUF][CCH][S2R][RW];  // 34.6 KB

    const int tx  = threadIdx.x;           // 0..7
    const int ty  = threadIdx.y;           // 0..15
    const int tid = ty * 8 + tx;

    const int tile_x = blockIdx.x * TW;
    const int tile_y = blockIdx.y * TH;
    const int g      = blockIdx.z % 3;
    const int n      = blockIdx.z / 3;     // n-major z for L2 locality
    const int dy0    = 3 * g;

    const float* f1n = f1 + (size_t)n * C_ * H_ * W_;
    const float* f2n = f2 + (size_t)n * C_ * H_ * W_;

    const uint32_t s1b = (uint32_t)__cvta_generic_to_shared(&s1[0][0][0][0]);
    const uint32_t s2b = (uint32_t)__cvta_generic_to_shared(&s2[0][0][0][0]);

    // ---- precompute chunk-invariant f2 staging descriptors (6 f4/thread) ----
    int  off2[6];
    int  sm2[6];
    bool pr2[6];
    bool act2[6];
#pragma unroll
    for (int i = 0; i < 6; i++) {
        int idx = tid + THREADS * i;
        act2[i] = (idx < F2_F4);
        int id  = act2[i] ? idx : 0;
        int c   = id / (S2R * RW / 4);
        int rem = id - c * (S2R * RW / 4);
        int r   = rem / (RW / 4);
        int q   = rem - r * (RW / 4);
        int gy  = tile_y + dy0 - 4 + r;
        bool valid = ((unsigned)gy < (unsigned)H_)
                   && !(q == 0 && tile_x == 0)
                   && !(q == 9 && tile_x + TW + 4 > W_);
        int gyc = valid ? gy : 0;
        off2[i] = (c * H_ + gyc) * W_ + tile_x - 4 + q * 4;
        if (q == 0 && tile_x == 0) off2[i] += 4;  // keep ptr in-bounds (sz=0)
        sm2[i]  = ((c * S2R + r) * RW + q * 4) * 4;
        pr2[i]  = valid;
    }

    // packed accumulators: pp=0 -> pixels (0,1), pp=1 -> (2,3)
    uint64_t acc0[DG][9], acc1[DG][9];
#pragma unroll
    for (int d = 0; d < DG; d++)
#pragma unroll
        for (int x = 0; x < 9; x++) { acc0[d][x] = 0ull; acc1[d][x] = 0ull; }

    auto stage = [&](int buf, int cb) {
        const float* f1c = f1n + (size_t)cb * CCH * H_ * W_;
        const float* f2c = f2n + (size_t)cb * CCH * H_ * W_;
        uint32_t d1 = s1b + (uint32_t)(buf * (CCH * TH * TW * 4));
        uint32_t d2 = s2b + (uint32_t)(buf * (CCH * S2R * RW * 4));
#pragma unroll
        for (int i = 0; i < F1_F4 / THREADS; i++) {
            int idx = tid + THREADS * i;
            int c   = idx >> 7;
            int rem = idx & 127;
            int r   = rem >> 3;
            int q   = rem & 7;
            cp_async16(d1 + (uint32_t)(((c * TH + r) * TW + q * 4) * 4),
                       f1c + ((size_t)c * H_ + tile_y + r) * W_ + tile_x + q * 4,
                       true);
        }
#pragma unroll
        for (int i = 0; i < 6; i++) {
            if (act2[i])
                cp_async16(d2 + (uint32_t)sm2[i], f2c + off2[i], pr2[i]);
        }
    };

    // ---- ring prologue: stage chunks 0 and 1 ----
    stage(0, 0); cp_commit();
    stage(1, 1); cp_commit();

    int buf  = 0;   // buffer holding chunk cb
    int bufs = 2;   // buffer to stage into (holds cb+2)

    for (int cb = 0; cb < NCHUNK; cb++) {
        cp_wait1();            // chunk cb's group complete for this thread
        __syncthreads();       // (a) cb's data CTA-visible; (b) all warps done
                               //     reading the restage target (used at cb-1)

        // stage cb+2 into the buffer consumed at cb-1 (cp.async overlaps fmas)
        if (cb + 2 < NCHUNK) stage(bufs, cb + 2);
        cp_commit();           // uniform group accounting (possibly empty)

        const float* s2base = &s2[buf][0][0][0];
        const float* s1base = &s1[buf][0][0][0];

#pragma unroll
        for (int c = 0; c < CCH; c++) {
            uint64_t a01, a23;
            {
                ulonglong2 av = *reinterpret_cast<const ulonglong2*>(
                    s1base + (size_t)(c * TH + ty) * TW + tx * 4);
                a01 = av.x; a23 = av.y;
            }
#pragma unroll
            for (int dyi = 0; dyi < DG; dyi++) {
                const float* row = s2base + (size_t)(c * S2R + ty + dyi) * RW + tx * 4;
                ulonglong2 e01 = *reinterpret_cast<const ulonglong2*>(row);
                ulonglong2 e23 = *reinterpret_cast<const ulonglong2*>(row + 4);
                ulonglong2 e45 = *reinterpret_cast<const ulonglong2*>(row + 8);
                uint64_t pe[6] = {e01.x, e01.y, e23.x, e23.y, e45.x, e45.y};

                // even-dx fma2s (operands are native pairs, no packs)
#pragma unroll
                for (int dx = 0; dx < 9; dx += 2) {
                    fma2(acc0[dyi][dx], a01, pe[dx >> 1]);
                    fma2(acc1[dyi][dx], a23, pe[(dx >> 1) + 1]);
                }

                // odd pairs: 5 packs from register halves (free upk)
                float r0, r1, r2, r3, r4, r5, r6, r7, r8, r9, r10, r11;
                upk(pe[0], r0, r1);  upk(pe[1], r2, r3);
                upk(pe[2], r4, r5);  upk(pe[3], r6, r7);
                upk(pe[4], r8, r9);  upk(pe[5], r10, r11);
                uint64_t po[5];
                po[0] = pk2(r1, r2);  po[1] = pk2(r3, r4);
                po[2] = pk2(r5, r6);  po[3] = pk2(r7, r8);
                po[4] = pk2(r9, r10);

#pragma unroll
                for (int dx = 1; dx < 9; dx += 2) {
                    fma2(acc0[dyi][dx], a01, po[dx >> 1]);
                    fma2(acc1[dyi][dx], a23, po[(dx >> 1) + 1]);
                }
            }
        }

        // advance ring
        buf  = (buf  == NBUF - 1) ? 0 : buf + 1;
        bufs = (bufs == NBUF - 1) ? 0 : bufs + 1;
    }

    // ---- epilogue ----
    const float inv = 1.0f / (float)C_;
    float* outn = out + (size_t)n * 81 * H_ * W_;
    const int y = tile_y + ty;
    const int x = tile_x + tx * 4;
#pragma unroll
    for (int dyi = 0; dyi < DG; dyi++)
#pragma unroll
        for (int dx = 0; dx < 9; dx++) {
            int k = (dy0 + dyi) * 9 + dx;
            float v0, v1, v2, v3;
            upk(acc0[dyi][dx], v0, v1);
            upk(acc1[dyi][dx], v2, v3);
            float4 v = make_float4(v0 * inv, v1 * inv, v2 * inv, v3 * inv);
            *reinterpret_cast<float4*>(outn + ((size_t)k * H_ + y) * W_ + x) = v;
        }
}

extern "C" void kernel_launch(void* const* d_in, const int* in_sizes, int n_in,
                              void* d_out, int out_size)
{
    const float* f1 = (const float*)d_in[0];
    const float* f2 = (const float*)d_in[1];
    float* out = (float*)d_out;

    dim3 block(8, 16);
    dim3 grid(W_ / TW, H_ / TH, N_ * 3);   // 7 x 6 x 24
    costvol_kernel<<<grid, block>>>(f1, f2, out);
}